// round 3
// baseline (speedup 1.0000x reference)
#include <cuda_runtime.h>
#include <math.h>

// Problem constants
#define BATCH   64
#define IN_D    256
#define MEM_D   128
#define NSLOT   4096
#define CPB     8                 // blocks (chunks) per batch
#define CHUNK   (NSLOT / CPB)     // 512 rows per block

// -------- scratch (no allocations allowed) --------
__device__ float g_v [BATCH * MEM_D];
__device__ float g_wq[BATCH * MEM_D];
__device__ float g_rq[BATCH * MEM_D];
__device__ float g_s [BATCH];
__device__ float g_ro[BATCH * MEM_D];

// per-(batch,chunk) softmax partials + sync counters
__device__ float g_pm1[BATCH * CPB];
__device__ float g_pz1[BATCH * CPB];
__device__ float g_pm2[BATCH * CPB];
__device__ float g_pz2[BATCH * CPB];
__device__ float g_ps2[BATCH * CPB];
__device__ int   g_cnt1[BATCH];
__device__ int   g_cnt2[BATCH];

__device__ __forceinline__ float warpSum(float v) {
#pragma unroll
    for (int o = 16; o; o >>= 1) v += __shfl_xor_sync(0xffffffffu, v, o);
    return v;
}
__device__ __forceinline__ float warpMax(float v) {
#pragma unroll
    for (int o = 16; o; o >>= 1) v = fmaxf(v, __shfl_xor_sync(0xffffffffu, v, o));
    return v;
}
__device__ __forceinline__ float blockSum(float v, float* sred) {
    v = warpSum(v);
    if ((threadIdx.x & 31) == 0) sred[threadIdx.x >> 5] = v;
    __syncthreads();
    float r = sred[0];
#pragma unroll
    for (int i = 1; i < 8; i++) r += sred[i];
    __syncthreads();
    return r;
}
__device__ __forceinline__ float blockMax(float v, float* sred) {
    v = warpMax(v);
    if ((threadIdx.x & 31) == 0) sred[threadIdx.x >> 5] = v;
    __syncthreads();
    float r = sred[0];
#pragma unroll
    for (int i = 1; i < 8; i++) r = fmaxf(r, sred[i]);
    __syncthreads();
    return r;
}

// ---------------------------------------------------------------------------
// Kernel 1: projections v, wq, rq (64x128, K=256); also resets sync state.
// grid 64, block 128
// ---------------------------------------------------------------------------
__global__ void proj_kernel(const float* __restrict__ x,
                            const float* __restrict__ Ww, const float* __restrict__ bw,
                            const float* __restrict__ Wq, const float* __restrict__ bq,
                            const float* __restrict__ Wr, const float* __restrict__ br) {
    const int b = blockIdx.x;
    const int t = threadIdx.x;                // 0..127
    __shared__ float sx[IN_D];
    sx[t]       = x[b * IN_D + t];
    sx[t + 128] = x[b * IN_D + t + 128];
    if (t == 0) { g_cnt1[b] = 0; g_cnt2[b] = 0; }
    __syncthreads();

    float aV = bw[t], aQ = bq[t], aR = br[t];
#pragma unroll 8
    for (int k = 0; k < IN_D; k++) {
        const float xv = sx[k];
        aV = fmaf(xv, Ww[k * MEM_D + t], aV);
        aQ = fmaf(xv, Wq[k * MEM_D + t], aQ);
        aR = fmaf(xv, Wr[k * MEM_D + t], aR);
    }
    g_v [b * MEM_D + t] = aV;
    g_wq[b * MEM_D + t] = aQ;
    g_rq[b * MEM_D + t] = aR;
    g_ro[b * MEM_D + t] = 0.0f;
}

// ---------------------------------------------------------------------------
// Kernel 2: FUSED dots + dual-softmax + weighted accumulation.
// grid = BATCH*CPB = 512 blocks, 256 threads (single wave; batch blocks
// contiguous in bid -> per-batch counter barrier is deadlock-free).
// Each block touches only its own 512-row (256KB) slice of `memory`,
// reading it twice in quick succession -> second read is L2-hot.
// ---------------------------------------------------------------------------
__global__ void __launch_bounds__(256)
fused_kernel(const float* __restrict__ mem) {
    const int b  = blockIdx.x >> 3;          // batch
    const int ch = blockIdx.x & 7;           // chunk within batch
    const int bi = blockIdx.x;               // partial index
    const int t  = threadIdx.x;
    const int lane = t & 31, w = t >> 5;     // 8 warps

    __shared__ float sd1[CHUNK];             // d1 -> ww -> c
    __shared__ float sd2[CHUNK];             // d2 -> rl
    __shared__ float swq[MEM_D];
    __shared__ float srq[MEM_D];
    __shared__ float sred[8];
    __shared__ float sbc[2];
    __shared__ float4 sacc[256];

    if (t < MEM_D) {
        swq[t] = g_wq[b * MEM_D + t];
        srq[t] = g_rq[b * MEM_D + t];
    }
    __syncthreads();

    const float4* mb = reinterpret_cast<const float4*>(
        mem + ((size_t)b * NSLOT + (size_t)ch * CHUNK) * MEM_D);
    const float4* swq4 = reinterpret_cast<const float4*>(swq);
    const float4* srq4 = reinterpret_cast<const float4*>(srq);

    // ---- Phase 1: thread-per-row dots d1 = mem.wq, d2 = mem.rq ----
#pragma unroll
    for (int rr = 0; rr < CHUNK; rr += 256) {
        const int row = rr + t;
        const float4* mrow = mb + (size_t)row * 32;
        float a = 0.0f, c = 0.0f;
#pragma unroll 8
        for (int i = 0; i < 32; i++) {
            const float4 m = mrow[i];
            const float4 q = swq4[i];
            const float4 r = srq4[i];
            a = fmaf(m.x, q.x, a); a = fmaf(m.y, q.y, a);
            a = fmaf(m.z, q.z, a); a = fmaf(m.w, q.w, a);
            c = fmaf(m.x, r.x, c); c = fmaf(m.y, r.y, c);
            c = fmaf(m.z, r.z, c); c = fmaf(m.w, r.w, c);
        }
        sd1[row] = a;
        sd2[row] = c;
    }

    // qv = v . rq for this batch (redundant per block, cheap)
    float qp = (t < MEM_D) ? g_v[b * MEM_D + t] * srq[t] : 0.0f;
    __syncthreads();                          // sd1/sd2 complete
    const float qv = blockSum(qp, sred);

    // ---- local write-softmax partials over this chunk ----
    float lm = fmaxf(sd1[t], sd1[t + 256]);
    const float m1 = blockMax(lm, sred);
    float lz = __expf(sd1[t] - m1) + __expf(sd1[t + 256] - m1);
    const float z1 = blockSum(lz, sred);

    // ---- cross-chunk combine #1 ----
    if (t == 0) {
        *(volatile float*)&g_pm1[bi] = m1;
        *(volatile float*)&g_pz1[bi] = z1;
        __threadfence();
        atomicAdd(&g_cnt1[b], 1);
        while (atomicAdd(&g_cnt1[b], 0) < CPB) __nanosleep(64);
        __threadfence();
        float M = -1e30f;
#pragma unroll
        for (int i = 0; i < CPB; i++)
            M = fmaxf(M, *(volatile float*)&g_pm1[b * CPB + i]);
        float Z = 0.0f;
#pragma unroll
        for (int i = 0; i < CPB; i++)
            Z += (*(volatile float*)&g_pz1[b * CPB + i]) *
                 __expf((*(volatile float*)&g_pm1[b * CPB + i]) - M);
        sbc[0] = M; sbc[1] = 1.0f / Z;
    }
    __syncthreads();
    const float M1 = sbc[0], invZ1 = sbc[1];

    // ---- ww, read-logits; local read-softmax partials ----
    float m2l = -1e30f;
#pragma unroll
    for (int i = 0; i < 2; i++) {
        const int n = t + i * 256;
        const float ww = __expf(sd1[n] - M1) * invZ1;
        const float d2v = sd2[n];
        const float rl = d2v - ww * (d2v - qv);
        sd1[n] = ww;
        sd2[n] = rl;
        m2l = fmaxf(m2l, rl);
    }
    const float m2 = blockMax(m2l, sred);
    float lz2 = 0.0f, ls2 = 0.0f;
#pragma unroll
    for (int i = 0; i < 2; i++) {
        const int n = t + i * 256;
        const float e = __expf(sd2[n] - m2);
        lz2 += e;
        ls2 += e * sd1[n];
    }
    const float z2 = blockSum(lz2, sred);
    const float s2 = blockSum(ls2, sred);

    // ---- cross-chunk combine #2 ----
    if (t == 0) {
        *(volatile float*)&g_pm2[bi] = m2;
        *(volatile float*)&g_pz2[bi] = z2;
        *(volatile float*)&g_ps2[bi] = s2;
        __threadfence();
        atomicAdd(&g_cnt2[b], 1);
        while (atomicAdd(&g_cnt2[b], 0) < CPB) __nanosleep(64);
        __threadfence();
        float M = -1e30f;
#pragma unroll
        for (int i = 0; i < CPB; i++)
            M = fmaxf(M, *(volatile float*)&g_pm2[b * CPB + i]);
        float Z = 0.0f, S = 0.0f;
#pragma unroll
        for (int i = 0; i < CPB; i++) {
            const float e = __expf((*(volatile float*)&g_pm2[b * CPB + i]) - M);
            Z += (*(volatile float*)&g_pz2[b * CPB + i]) * e;
            S += (*(volatile float*)&g_ps2[b * CPB + i]) * e;
        }
        sbc[0] = M; sbc[1] = 1.0f / Z;
        if (ch == 0) g_s[b] = S / Z;
    }
    __syncthreads();
    const float M2 = sbc[0], invZ2 = sbc[1];

    // ---- c_n = rw_n * (1 - ww_n) ----
#pragma unroll
    for (int i = 0; i < 2; i++) {
        const int n = t + i * 256;
        sd1[n] = __expf(sd2[n] - M2) * invZ2 * (1.0f - sd1[n]);
    }
    __syncthreads();

    // ---- Phase 2: read_out partial = sum_n c_n * mem_n  (L2-hot re-read) ----
    float4 acc = make_float4(0.f, 0.f, 0.f, 0.f);
#pragma unroll 4
    for (int n = w; n < CHUNK; n += 8) {
        const float cv = sd1[n];
        const float4 m = mb[(size_t)n * 32 + lane];
        acc.x = fmaf(cv, m.x, acc.x);
        acc.y = fmaf(cv, m.y, acc.y);
        acc.z = fmaf(cv, m.z, acc.z);
        acc.w = fmaf(cv, m.w, acc.w);
    }
    sacc[t] = acc;
    __syncthreads();
    if (t < 32) {
        float4 s = sacc[t];
#pragma unroll
        for (int r = 1; r < 8; r++) {
            const float4 u = sacc[r * 32 + t];
            s.x += u.x; s.y += u.y; s.z += u.z; s.w += u.w;
        }
        float* dst = g_ro + b * MEM_D + t * 4;
        atomicAdd(dst + 0, s.x);
        atomicAdd(dst + 1, s.y);
        atomicAdd(dst + 2, s.z);
        atomicAdd(dst + 3, s.w);
    }
}

// ---------------------------------------------------------------------------
// Kernel 3: out[b,o] = b_ro[o] + sum_d (g_ro[b,d] + s[b]*v[b,d]) * W_ro[d,o]
// grid 64, block 256.
// ---------------------------------------------------------------------------
__global__ void out_kernel(const float* __restrict__ Wro,
                           const float* __restrict__ bro,
                           float* __restrict__ out) {
    const int b = blockIdx.x;
    const int t = threadIdx.x;               // 0..255
    __shared__ float sr[MEM_D];
    if (t < MEM_D) sr[t] = g_ro[b * MEM_D + t] + g_s[b] * g_v[b * MEM_D + t];
    __syncthreads();

    float acc = bro[t];
#pragma unroll 8
    for (int d = 0; d < MEM_D; d++)
        acc = fmaf(sr[d], Wro[d * IN_D + t], acc);
    out[b * IN_D + t] = acc;
}

// ---------------------------------------------------------------------------
extern "C" void kernel_launch(void* const* d_in, const int* in_sizes, int n_in,
                              void* d_out, int out_size) {
    const float* x   = (const float*)d_in[0];
    const float* mem = (const float*)d_in[1];
    const float* Ww  = (const float*)d_in[2];
    const float* bw  = (const float*)d_in[3];
    const float* Wq  = (const float*)d_in[4];
    const float* bq  = (const float*)d_in[5];
    const float* Wr  = (const float*)d_in[6];
    const float* br  = (const float*)d_in[7];
    const float* Wro = (const float*)d_in[8];
    const float* bro = (const float*)d_in[9];
    float* out = (float*)d_out;

    proj_kernel<<<BATCH, 128>>>(x, Ww, bw, Wq, bq, Wr, br);
    fused_kernel<<<BATCH * CPB, 256>>>(mem);
    out_kernel<<<BATCH, 256>>>(Wro, bro, out);
}

// round 4
// speedup vs baseline: 1.2331x; 1.2331x over previous
#include <cuda_runtime.h>
#include <math.h>

// Problem constants
#define BATCH   64
#define IN_D    256
#define MEM_D   128
#define NSLOT   4096
#define CPB     32                 // chunks (blocks) per batch
#define CHUNK   (NSLOT / CPB)      // 128 rows per block
#define PITCH4  40                 // float4 pitch per row in smem tile (640B, bank-safe)

// dynamic smem: tile + racc (float4), then floats
#define SMEM_FUSED ((CHUNK * PITCH4 + 8 * 32) * 16 + 2112)

// -------- scratch (no device allocations allowed) --------
__device__ float g_v [BATCH * MEM_D];
__device__ float g_wq[BATCH * MEM_D];
__device__ float g_rq[BATCH * MEM_D];
__device__ float g_s [BATCH];
__device__ float g_ro[BATCH * MEM_D];

__device__ float g_pm1[BATCH * CPB];
__device__ float g_pz1[BATCH * CPB];
__device__ float g_pm2[BATCH * CPB];
__device__ float g_pz2[BATCH * CPB];
__device__ float g_ps2[BATCH * CPB];
__device__ int   g_cnt1[BATCH];
__device__ int   g_cnt2[BATCH];

__device__ __forceinline__ float warpSum(float v) {
#pragma unroll
    for (int o = 16; o; o >>= 1) v += __shfl_xor_sync(0xffffffffu, v, o);
    return v;
}
__device__ __forceinline__ float warpMax(float v) {
#pragma unroll
    for (int o = 16; o; o >>= 1) v = fmaxf(v, __shfl_xor_sync(0xffffffffu, v, o));
    return v;
}
// block reduce for 256 threads (8 warps)
__device__ __forceinline__ float blockSum(float v, float* sred) {
    v = warpSum(v);
    if ((threadIdx.x & 31) == 0) sred[threadIdx.x >> 5] = v;
    __syncthreads();
    float r = sred[0];
#pragma unroll
    for (int i = 1; i < 8; i++) r += sred[i];
    __syncthreads();
    return r;
}
__device__ __forceinline__ float blockMax(float v, float* sred) {
    v = warpMax(v);
    if ((threadIdx.x & 31) == 0) sred[threadIdx.x >> 5] = v;
    __syncthreads();
    float r = sred[0];
#pragma unroll
    for (int i = 1; i < 8; i++) r = fmaxf(r, sred[i]);
    __syncthreads();
    return r;
}

// ---------------------------------------------------------------------------
// Kernel 1: projections. grid = 192 (64 batches x 3 matrices), block 256.
// Two threads per output column, each covering half of K=256.
// Also resets sync counters and zeroes g_ro (m==0 blocks).
// ---------------------------------------------------------------------------
__global__ void __launch_bounds__(256)
proj_kernel(const float* __restrict__ x,
            const float* __restrict__ Ww, const float* __restrict__ bw,
            const float* __restrict__ Wq, const float* __restrict__ bq,
            const float* __restrict__ Wr, const float* __restrict__ br) {
    const int b = blockIdx.x & 63;
    const int m = blockIdx.x >> 6;           // 0,1,2
    const int t = threadIdx.x;

    const float* W    = (m == 0) ? Ww : ((m == 1) ? Wq : Wr);
    const float* bias = (m == 0) ? bw : ((m == 1) ? bq : br);
    float* dst        = (m == 0) ? g_v : ((m == 1) ? g_wq : g_rq);

    __shared__ float sx[IN_D];
    __shared__ float sp[256];
    sx[t] = x[b * IN_D + t];
    if (m == 0 && t == 0) { g_cnt1[b] = 0; g_cnt2[b] = 0; }
    if (m == 0 && t < MEM_D) g_ro[b * MEM_D + t] = 0.0f;
    __syncthreads();

    const int o = t & 127;
    const int h = t >> 7;                    // K half
    float acc = 0.0f;
    const int k0 = h * 128;
#pragma unroll 8
    for (int k = 0; k < 128; k++)
        acc = fmaf(sx[k0 + k], W[(k0 + k) * MEM_D + o], acc);
    sp[t] = acc;
    __syncthreads();
    if (t < MEM_D)
        dst[b * MEM_D + t] = sp[t] + sp[128 + t] + bias[t];
}

// ---------------------------------------------------------------------------
// Kernel 2: FUSED single-HBM-pass. grid = 2048 (64 x 32 chunks), block 256.
// Each block: stream its 128-row (64KB) slice ONCE from global, computing
// per-row dots on the fly and staging the tile in padded smem; per-batch
// softmax combine via counter barrier; weighted accumulation from SMEM.
// 2 blocks/SM (88KB smem each). Per-batch barrier groups are contiguous in
// bid; in-order dispatch => lowest unfinished batch always fully resident.
// ---------------------------------------------------------------------------
__global__ void __launch_bounds__(256, 2)
fused_kernel(const float* __restrict__ mem) {
    const int b  = blockIdx.x >> 5;
    const int ch = blockIdx.x & 31;
    const int bi = blockIdx.x;
    const int t  = threadIdx.x;
    const int lane = t & 31, w = t >> 5;     // 8 warps
    const int s = lane & 7, rsub = lane >> 3; // quarter-warp layout

    extern __shared__ float4 sm4[];
    float4* tile = sm4;                              // CHUNK*PITCH4 = 5120
    float4* racc = sm4 + CHUNK * PITCH4;             // 8*32 = 256
    float*  sd1  = (float*)(racc + 256);             // CHUNK
    float*  sd2  = sd1 + CHUNK;                      // CHUNK
    float*  swq  = sd2 + CHUNK;                      // 128
    float*  srq  = swq + MEM_D;                      // 128
    float*  sred = srq + MEM_D;                      // 8
    float*  sbc  = sred + 8;                         // 2

    if (t < MEM_D) {
        swq[t] = g_wq[b * MEM_D + t];
        srq[t] = g_rq[b * MEM_D + t];
    }
    __syncthreads();

    // per-thread query slices (cols (j*8+s)*4 .. +3)
    float4 q4[4], r4[4];
#pragma unroll
    for (int j = 0; j < 4; j++) {
        q4[j] = reinterpret_cast<const float4*>(swq)[j * 8 + s];
        r4[j] = reinterpret_cast<const float4*>(srq)[j * 8 + s];
    }

    const float4* mb = reinterpret_cast<const float4*>(mem) +
                       ((size_t)b * NSLOT + (size_t)ch * CHUNK) * 32;

    // ---- Phase 1: load + dots + stage tile. Warp covers 16 rows (4 per g). ----
#pragma unroll 2
    for (int g = 0; g < 4; g++) {
        const int lr = w * 16 + g * 4 + rsub;        // 0..127
        const float4* grow = mb + (size_t)lr * 32;
        float4 mv[4];
#pragma unroll
        for (int j = 0; j < 4; j++) mv[j] = grow[j * 8 + s];
        float a = 0.0f, c = 0.0f;
#pragma unroll
        for (int j = 0; j < 4; j++) {
            tile[lr * PITCH4 + j * 8 + s] = mv[j];
            a = fmaf(mv[j].x, q4[j].x, a); a = fmaf(mv[j].y, q4[j].y, a);
            a = fmaf(mv[j].z, q4[j].z, a); a = fmaf(mv[j].w, q4[j].w, a);
            c = fmaf(mv[j].x, r4[j].x, c); c = fmaf(mv[j].y, r4[j].y, c);
            c = fmaf(mv[j].z, r4[j].z, c); c = fmaf(mv[j].w, r4[j].w, c);
        }
#pragma unroll
        for (int o = 4; o; o >>= 1) {                // reduce over s (8 lanes)
            a += __shfl_xor_sync(0xffffffffu, a, o);
            c += __shfl_xor_sync(0xffffffffu, c, o);
        }
        if (s == 0) { sd1[lr] = a; sd2[lr] = c; }
    }

    // qv = v . rq
    float qp = (t < MEM_D) ? g_v[b * MEM_D + t] * srq[t] : 0.0f;
    const float qv = blockSum(qp, sred);             // internal syncs publish sd1/sd2

    // ---- local write-softmax partials over this chunk ----
    const float m1 = blockMax((t < CHUNK) ? sd1[t] : -1e30f, sred);
    const float z1 = blockSum((t < CHUNK) ? __expf(sd1[t] - m1) : 0.0f, sred);

    // ---- cross-chunk combine #1 ----
    if (t == 0) {
        *(volatile float*)&g_pm1[bi] = m1;
        *(volatile float*)&g_pz1[bi] = z1;
        __threadfence();
        atomicAdd(&g_cnt1[b], 1);
        while (atomicAdd(&g_cnt1[b], 0) < CPB) __nanosleep(64);
        __threadfence();
    }
    __syncthreads();
    if (t < CPB) {                                   // warp 0 combines in parallel
        const float pm = *(volatile float*)&g_pm1[b * CPB + t];
        const float pz = *(volatile float*)&g_pz1[b * CPB + t];
        const float M  = warpMax(pm);
        const float Z  = warpSum(pz * __expf(pm - M));
        if (t == 0) { sbc[0] = M; sbc[1] = 1.0f / Z; }
    }
    __syncthreads();
    const float M1 = sbc[0], invZ1 = sbc[1];
    __syncthreads();

    // ---- ww, read-logits; local read-softmax partials ----
    float m2l = -1e30f;
    if (t < CHUNK) {
        const float ww = __expf(sd1[t] - M1) * invZ1;
        const float d2v = sd2[t];
        const float rl = d2v - ww * (d2v - qv);
        sd1[t] = ww;
        sd2[t] = rl;
        m2l = rl;
    }
    const float m2 = blockMax(m2l, sred);
    float lz2 = 0.0f, ls2 = 0.0f;
    if (t < CHUNK) {
        const float e = __expf(sd2[t] - m2);
        lz2 = e;
        ls2 = e * sd1[t];
    }
    const float z2 = blockSum(lz2, sred);
    const float s2 = blockSum(ls2, sred);

    // ---- cross-chunk combine #2 ----
    if (t == 0) {
        *(volatile float*)&g_pm2[bi] = m2;
        *(volatile float*)&g_pz2[bi] = z2;
        *(volatile float*)&g_ps2[bi] = s2;
        __threadfence();
        atomicAdd(&g_cnt2[b], 1);
        while (atomicAdd(&g_cnt2[b], 0) < CPB) __nanosleep(64);
        __threadfence();
    }
    __syncthreads();
    if (t < CPB) {
        const float pm = *(volatile float*)&g_pm2[b * CPB + t];
        const float pz = *(volatile float*)&g_pz2[b * CPB + t];
        const float ps = *(volatile float*)&g_ps2[b * CPB + t];
        const float M  = warpMax(pm);
        const float e  = __expf(pm - M);
        const float Z  = warpSum(pz * e);
        const float S  = warpSum(ps * e);
        if (t == 0) {
            sbc[0] = M; sbc[1] = 1.0f / Z;
            if (ch == 0) g_s[b] = S / Z;
        }
    }
    __syncthreads();
    const float M2 = sbc[0], invZ2 = sbc[1];
    __syncthreads();

    // ---- c_n = rw_n * (1 - ww_n) ----
    if (t < CHUNK)
        sd1[t] = __expf(sd2[t] - M2) * invZ2 * (1.0f - sd1[t]);
    __syncthreads();

    // ---- Phase 2: read_out partial from SMEM tile (no HBM re-read) ----
    float4 acc[4];
#pragma unroll
    for (int j = 0; j < 4; j++) acc[j] = make_float4(0.f, 0.f, 0.f, 0.f);
#pragma unroll
    for (int g = 0; g < 4; g++) {
        const int lr = w * 16 + g * 4 + rsub;
        const float cv = sd1[lr];
#pragma unroll
        for (int j = 0; j < 4; j++) {
            const float4 m = tile[lr * PITCH4 + j * 8 + s];
            acc[j].x = fmaf(cv, m.x, acc[j].x);
            acc[j].y = fmaf(cv, m.y, acc[j].y);
            acc[j].z = fmaf(cv, m.z, acc[j].z);
            acc[j].w = fmaf(cv, m.w, acc[j].w);
        }
    }
    // reduce across the 4 row-subgroups (lanes xor 8, 16)
#pragma unroll
    for (int o = 8; o <= 16; o <<= 1) {
#pragma unroll
        for (int j = 0; j < 4; j++) {
            acc[j].x += __shfl_xor_sync(0xffffffffu, acc[j].x, o);
            acc[j].y += __shfl_xor_sync(0xffffffffu, acc[j].y, o);
            acc[j].z += __shfl_xor_sync(0xffffffffu, acc[j].z, o);
            acc[j].w += __shfl_xor_sync(0xffffffffu, acc[j].w, o);
        }
    }
    if (rsub == 0) {
#pragma unroll
        for (int j = 0; j < 4; j++) racc[w * 32 + j * 8 + s] = acc[j];
    }
    __syncthreads();
    if (t < 32) {
        float4 ssum = racc[t];
#pragma unroll
        for (int w2 = 1; w2 < 8; w2++) {
            const float4 u = racc[w2 * 32 + t];
            ssum.x += u.x; ssum.y += u.y; ssum.z += u.z; ssum.w += u.w;
        }
        float* dst = g_ro + b * MEM_D + t * 4;
        atomicAdd(dst + 0, ssum.x);
        atomicAdd(dst + 1, ssum.y);
        atomicAdd(dst + 2, ssum.z);
        atomicAdd(dst + 3, ssum.w);
    }
}

// ---------------------------------------------------------------------------
// Kernel 3: out[b,o] = b_ro[o] + sum_d (g_ro[b,d] + s[b]*v[b,d]) * W_ro[d,o]
// grid 64, block 512 (2 threads per output, K halves).
// ---------------------------------------------------------------------------
__global__ void __launch_bounds__(512)
out_kernel(const float* __restrict__ Wro,
           const float* __restrict__ bro,
           float* __restrict__ out) {
    const int b = blockIdx.x;
    const int t = threadIdx.x;               // 0..511
    __shared__ float sr[MEM_D];
    __shared__ float so[512];
    if (t < MEM_D) sr[t] = g_ro[b * MEM_D + t] + g_s[b] * g_v[b * MEM_D + t];
    __syncthreads();

    const int o = t & 255;
    const int h = t >> 8;
    float acc = 0.0f;
    const int d0 = h * 64;
#pragma unroll 8
    for (int d = 0; d < 64; d++)
        acc = fmaf(sr[d0 + d], Wro[(d0 + d) * IN_D + o], acc);
    so[t] = acc;
    __syncthreads();
    if (t < IN_D)
        out[b * IN_D + t] = so[t] + so[256 + t] + bro[t];
}

// ---------------------------------------------------------------------------
extern "C" void kernel_launch(void* const* d_in, const int* in_sizes, int n_in,
                              void* d_out, int out_size) {
    const float* x   = (const float*)d_in[0];
    const float* mem = (const float*)d_in[1];
    const float* Ww  = (const float*)d_in[2];
    const float* bw  = (const float*)d_in[3];
    const float* Wq  = (const float*)d_in[4];
    const float* bq  = (const float*)d_in[5];
    const float* Wr  = (const float*)d_in[6];
    const float* br  = (const float*)d_in[7];
    const float* Wro = (const float*)d_in[8];
    const float* bro = (const float*)d_in[9];
    float* out = (float*)d_out;

    cudaFuncSetAttribute(fused_kernel,
                         cudaFuncAttributeMaxDynamicSharedMemorySize, SMEM_FUSED);

    proj_kernel<<<192, 256>>>(x, Ww, bw, Wq, bq, Wr, br);
    fused_kernel<<<BATCH * CPB, 256, SMEM_FUSED>>>(mem);
    out_kernel<<<BATCH, 512>>>(Wro, bro, out);
}

// round 5
// speedup vs baseline: 1.8187x; 1.4749x over previous
#include <cuda_runtime.h>
#include <math.h>

// Problem constants
#define BATCH   64
#define IN_D    256
#define MEM_D   128
#define NSLOT   4096
#define CPB     8                  // chunks (blocks) per batch -> single wave
#define CHUNK   (NSLOT / CPB)      // 512 rows per block

// -------- scratch (no device allocations allowed) --------
__device__ float g_v [BATCH * MEM_D];
__device__ float g_wq[BATCH * MEM_D];
__device__ float g_rq[BATCH * MEM_D];
__device__ float g_s [BATCH];
__device__ float g_ro[BATCH * MEM_D];

__device__ float g_pm1[BATCH * CPB];
__device__ float g_pz1[BATCH * CPB];
__device__ float g_pm2[BATCH * CPB];
__device__ float g_pz2[BATCH * CPB];
__device__ float g_ps2[BATCH * CPB];
__device__ int   g_cnt1[BATCH];
__device__ int   g_cnt2[BATCH];

__device__ __forceinline__ float warpSum(float v) {
#pragma unroll
    for (int o = 16; o; o >>= 1) v += __shfl_xor_sync(0xffffffffu, v, o);
    return v;
}
__device__ __forceinline__ float warpMax(float v) {
#pragma unroll
    for (int o = 16; o; o >>= 1) v = fmaxf(v, __shfl_xor_sync(0xffffffffu, v, o));
    return v;
}
// block reduce for 256 threads (8 warps)
__device__ __forceinline__ float blockSum(float v, float* sred) {
    v = warpSum(v);
    if ((threadIdx.x & 31) == 0) sred[threadIdx.x >> 5] = v;
    __syncthreads();
    float r = sred[0];
#pragma unroll
    for (int i = 1; i < 8; i++) r += sred[i];
    __syncthreads();
    return r;
}
__device__ __forceinline__ float blockMax(float v, float* sred) {
    v = warpMax(v);
    if ((threadIdx.x & 31) == 0) sred[threadIdx.x >> 5] = v;
    __syncthreads();
    float r = sred[0];
#pragma unroll
    for (int i = 1; i < 8; i++) r = fmaxf(r, sred[i]);
    __syncthreads();
    return r;
}

// ---------------------------------------------------------------------------
// Kernel 1: projections. grid = 192 (64 batches x 3 matrices), block 512.
// Four threads per output column (K quarters of 64) -> short latency chain.
// Also resets sync counters and zeroes g_ro (m==0 blocks).
// ---------------------------------------------------------------------------
__global__ void __launch_bounds__(512)
proj_kernel(const float* __restrict__ x,
            const float* __restrict__ Ww, const float* __restrict__ bw,
            const float* __restrict__ Wq, const float* __restrict__ bq,
            const float* __restrict__ Wr, const float* __restrict__ br) {
    const int b = blockIdx.x & 63;
    const int m = blockIdx.x >> 6;           // 0,1,2
    const int t = threadIdx.x;               // 0..511

    const float* W    = (m == 0) ? Ww : ((m == 1) ? Wq : Wr);
    const float* bias = (m == 0) ? bw : ((m == 1) ? bq : br);
    float* dst        = (m == 0) ? g_v : ((m == 1) ? g_wq : g_rq);

    __shared__ float sx[IN_D];
    __shared__ float sp[512];
    if (t < IN_D) sx[t] = x[b * IN_D + t];
    if (m == 0 && t == 0) { g_cnt1[b] = 0; g_cnt2[b] = 0; }
    if (m == 0 && t < MEM_D) g_ro[b * MEM_D + t] = 0.0f;
    __syncthreads();

    const int o  = t & 127;
    const int q  = t >> 7;                   // K quarter 0..3
    const int k0 = q * 64;
    float acc = 0.0f;
#pragma unroll 8
    for (int k = 0; k < 64; k++)
        acc = fmaf(sx[k0 + k], W[(k0 + k) * MEM_D + o], acc);
    sp[t] = acc;
    __syncthreads();
    if (t < MEM_D)
        dst[b * MEM_D + t] = sp[t] + sp[128 + t] + sp[256 + t] + sp[384 + t]
                             + bias[t];
}

// ---------------------------------------------------------------------------
// Kernel 2: FUSED dots + dual-softmax + accumulation, SINGLE WAVE.
// grid = 512 (64 batches x 8 chunks), block 256, 4 blocks/SM -> all resident.
// Phase 1 streams the 256KB slice once (coalesced warp-per-4-rows);
// phase 2 re-reads the same slice (mostly L2-hot) for the weighted sum.
// ---------------------------------------------------------------------------
__global__ void __launch_bounds__(256, 4)
fused_kernel(const float* __restrict__ mem) {
    const int b  = blockIdx.x >> 3;
    const int ch = blockIdx.x & 7;
    const int bi = blockIdx.x;
    const int t  = threadIdx.x;
    const int lane = t & 31, w = t >> 5;      // 8 warps
    const int s = lane & 7, rsub = lane >> 3; // quarter-warp layout

    __shared__ float  sd1[CHUNK];             // d1 -> ww -> c
    __shared__ float  sd2[CHUNK];             // d2 -> rl
    __shared__ float  swq[MEM_D];
    __shared__ float  srq[MEM_D];
    __shared__ float  sred[8];
    __shared__ float  sbc[2];
    __shared__ float4 racc[256];

    if (t < MEM_D) {
        swq[t] = g_wq[b * MEM_D + t];
        srq[t] = g_rq[b * MEM_D + t];
    }
    __syncthreads();

    // per-thread query slices (cols (j*8+s)*4 .. +3)
    float4 q4[4], r4[4];
#pragma unroll
    for (int j = 0; j < 4; j++) {
        q4[j] = reinterpret_cast<const float4*>(swq)[j * 8 + s];
        r4[j] = reinterpret_cast<const float4*>(srq)[j * 8 + s];
    }

    const float4* mb = reinterpret_cast<const float4*>(mem) +
                       ((size_t)b * NSLOT + (size_t)ch * CHUNK) * 32;

    // ---- Phase 1: coalesced dots d1 = mem.wq, d2 = mem.rq ----
    // Warp covers 4 rows per iteration: lane (rsub, s) reads row r0+rsub,
    // float4 cols j*8+s. 16 iterations cover 512 rows.
#pragma unroll 2
    for (int it = 0; it < 16; it++) {
        const int r0 = it * 32 + w * 4 + rsub;
        const float4* grow = mb + (size_t)r0 * 32;
        float a = 0.0f, c = 0.0f;
#pragma unroll
        for (int j = 0; j < 4; j++) {
            const float4 m = grow[j * 8 + s];
            a = fmaf(m.x, q4[j].x, a); a = fmaf(m.y, q4[j].y, a);
            a = fmaf(m.z, q4[j].z, a); a = fmaf(m.w, q4[j].w, a);
            c = fmaf(m.x, r4[j].x, c); c = fmaf(m.y, r4[j].y, c);
            c = fmaf(m.z, r4[j].z, c); c = fmaf(m.w, r4[j].w, c);
        }
#pragma unroll
        for (int o = 4; o; o >>= 1) {         // reduce over s (8 lanes)
            a += __shfl_xor_sync(0xffffffffu, a, o);
            c += __shfl_xor_sync(0xffffffffu, c, o);
        }
        if (s == 0) { sd1[r0] = a; sd2[r0] = c; }
    }

    // qv = v . rq
    float qp = (t < MEM_D) ? g_v[b * MEM_D + t] * srq[t] : 0.0f;
    __syncthreads();                          // publish sd1/sd2
    const float qv = blockSum(qp, sred);

    // ---- local write-softmax partials (2 elems per thread) ----
    const float m1 = blockMax(fmaxf(sd1[t], sd1[t + 256]), sred);
    const float z1 = blockSum(__expf(sd1[t] - m1) + __expf(sd1[t + 256] - m1),
                              sred);

    // ---- cross-chunk combine #1 ----
    if (t == 0) {
        *(volatile float*)&g_pm1[bi] = m1;
        *(volatile float*)&g_pz1[bi] = z1;
        __threadfence();
        atomicAdd(&g_cnt1[b], 1);
        while (atomicAdd(&g_cnt1[b], 0) < CPB) __nanosleep(32);
        __threadfence();
    }
    __syncthreads();
    if (t < 32) {
        const float pm = (t < CPB) ? *(volatile float*)&g_pm1[b * CPB + t] : -1e30f;
        const float pz = (t < CPB) ? *(volatile float*)&g_pz1[b * CPB + t] : 0.0f;
        const float M  = warpMax(pm);
        const float Z  = warpSum(pz * __expf(pm - M));
        if (t == 0) { sbc[0] = M; sbc[1] = 1.0f / Z; }
    }
    __syncthreads();
    const float M1 = sbc[0], invZ1 = sbc[1];

    // ---- ww, read-logits; local read-softmax partials ----
    float m2l = -1e30f;
#pragma unroll
    for (int i = 0; i < 2; i++) {
        const int n = t + i * 256;
        const float ww = __expf(sd1[n] - M1) * invZ1;
        const float d2v = sd2[n];
        const float rl = d2v - ww * (d2v - qv);
        sd1[n] = ww;
        sd2[n] = rl;
        m2l = fmaxf(m2l, rl);
    }
    const float m2 = blockMax(m2l, sred);
    float lz2 = 0.0f, ls2 = 0.0f;
#pragma unroll
    for (int i = 0; i < 2; i++) {
        const int n = t + i * 256;
        const float e = __expf(sd2[n] - m2);
        lz2 += e;
        ls2 += e * sd1[n];
    }
    const float z2 = blockSum(lz2, sred);
    const float s2 = blockSum(ls2, sred);

    // ---- cross-chunk combine #2 ----
    if (t == 0) {
        *(volatile float*)&g_pm2[bi] = m2;
        *(volatile float*)&g_pz2[bi] = z2;
        *(volatile float*)&g_ps2[bi] = s2;
        __threadfence();
        atomicAdd(&g_cnt2[b], 1);
        while (atomicAdd(&g_cnt2[b], 0) < CPB) __nanosleep(32);
        __threadfence();
    }
    __syncthreads();
    if (t < 32) {
        const float pm = (t < CPB) ? *(volatile float*)&g_pm2[b * CPB + t] : -1e30f;
        const float pz = (t < CPB) ? *(volatile float*)&g_pz2[b * CPB + t] : 0.0f;
        const float ps = (t < CPB) ? *(volatile float*)&g_ps2[b * CPB + t] : 0.0f;
        const float M  = warpMax(pm);
        const float e  = __expf(pm - M);
        const float Z  = warpSum(pz * e);
        const float S  = warpSum(ps * e);
        if (t == 0) {
            sbc[0] = M; sbc[1] = 1.0f / Z;
            if (ch == 0) g_s[b] = S / Z;
        }
    }
    __syncthreads();
    const float M2 = sbc[0], invZ2 = sbc[1];
    __syncthreads();

    // ---- c_n = rw_n * (1 - ww_n) ----
#pragma unroll
    for (int i = 0; i < 2; i++) {
        const int n = t + i * 256;
        sd1[n] = __expf(sd2[n] - M2) * invZ2 * (1.0f - sd1[n]);
    }
    __syncthreads();

    // ---- Phase 2: weighted re-read (L2-hot), same coalesced pattern ----
    float4 acc[4];
#pragma unroll
    for (int j = 0; j < 4; j++) acc[j] = make_float4(0.f, 0.f, 0.f, 0.f);
#pragma unroll 2
    for (int it = 0; it < 16; it++) {
        const int r0 = it * 32 + w * 4 + rsub;
        const float cv = sd1[r0];
        const float4* grow = mb + (size_t)r0 * 32;
#pragma unroll
        for (int j = 0; j < 4; j++) {
            const float4 m = grow[j * 8 + s];
            acc[j].x = fmaf(cv, m.x, acc[j].x);
            acc[j].y = fmaf(cv, m.y, acc[j].y);
            acc[j].z = fmaf(cv, m.z, acc[j].z);
            acc[j].w = fmaf(cv, m.w, acc[j].w);
        }
    }
    // reduce across the 4 row-subgroups (lanes xor 8, 16)
#pragma unroll
    for (int o = 8; o <= 16; o <<= 1) {
#pragma unroll
        for (int j = 0; j < 4; j++) {
            acc[j].x += __shfl_xor_sync(0xffffffffu, acc[j].x, o);
            acc[j].y += __shfl_xor_sync(0xffffffffu, acc[j].y, o);
            acc[j].z += __shfl_xor_sync(0xffffffffu, acc[j].z, o);
            acc[j].w += __shfl_xor_sync(0xffffffffu, acc[j].w, o);
        }
    }
    if (rsub == 0) {
#pragma unroll
        for (int j = 0; j < 4; j++) racc[w * 32 + j * 8 + s] = acc[j];
    }
    __syncthreads();
    if (t < 32) {
        float4 ssum = racc[t];
#pragma unroll
        for (int w2 = 1; w2 < 8; w2++) {
            const float4 u = racc[w2 * 32 + t];
            ssum.x += u.x; ssum.y += u.y; ssum.z += u.z; ssum.w += u.w;
        }
        float* dst = g_ro + b * MEM_D + t * 4;
        atomicAdd(dst + 0, ssum.x);
        atomicAdd(dst + 1, ssum.y);
        atomicAdd(dst + 2, ssum.z);
        atomicAdd(dst + 3, ssum.w);
    }
}

// ---------------------------------------------------------------------------
// Kernel 3: out[b,o] = b_ro[o] + sum_d (g_ro[b,d] + s[b]*v[b,d]) * W_ro[d,o]
// grid 64, block 512 (2 threads per output, K halves).
// ---------------------------------------------------------------------------
__global__ void __launch_bounds__(512)
out_kernel(const float* __restrict__ Wro,
           const float* __restrict__ bro,
           float* __restrict__ out) {
    const int b = blockIdx.x;
    const int t = threadIdx.x;               // 0..511
    __shared__ float sr[MEM_D];
    __shared__ float so[512];
    if (t < MEM_D) sr[t] = g_ro[b * MEM_D + t] + g_s[b] * g_v[b * MEM_D + t];
    __syncthreads();

    const int o = t & 255;
    const int h = t >> 8;
    float acc = 0.0f;
    const int d0 = h * 64;
#pragma unroll 8
    for (int d = 0; d < 64; d++)
        acc = fmaf(sr[d0 + d], Wro[(d0 + d) * IN_D + o], acc);
    so[t] = acc;
    __syncthreads();
    if (t < IN_D)
        out[b * IN_D + t] = so[t] + so[256 + t] + bro[t];
}

// ---------------------------------------------------------------------------
extern "C" void kernel_launch(void* const* d_in, const int* in_sizes, int n_in,
                              void* d_out, int out_size) {
    const float* x   = (const float*)d_in[0];
    const float* mem = (const float*)d_in[1];
    const float* Ww  = (const float*)d_in[2];
    const float* bw  = (const float*)d_in[3];
    const float* Wq  = (const float*)d_in[4];
    const float* bq  = (const float*)d_in[5];
    const float* Wr  = (const float*)d_in[6];
    const float* br  = (const float*)d_in[7];
    const float* Wro = (const float*)d_in[8];
    const float* bro = (const float*)d_in[9];
    float* out = (float*)d_out;

    proj_kernel<<<192, 512>>>(x, Ww, bw, Wq, bq, Wr, br);
    fused_kernel<<<BATCH * CPB, 256>>>(mem);
    out_kernel<<<BATCH, 512>>>(Wro, bro, out);
}